// round 3
// baseline (speedup 1.0000x reference)
#include <cuda_runtime.h>
#include <cstdint>

// Output: R[b, s, 64, 64] fp32, B*S = 16384 matrices of 16 KB each.
// Only 128 floats per matrix are nonzero (32 diagonal 2x2 rotation blocks),
// and the zero pattern is identical for every matrix.
//
// Persistent CTAs: zero two 16 KB SMEM buffers ONCE, then per matrix
// overwrite only the 64 (sin,cos) pairs and stream the buffer to GMEM
// with cp.async.bulk. Double-buffered so the TMA drain of one buffer
// overlaps pair-fill of the other.

static constexpr unsigned NBUF    = 2;
static constexpr unsigned THREADS = 64;

__global__ void __launch_bounds__(THREADS) rope2d_persist_kernel(
    const float* __restrict__ spa,    // (n_mat, 2)
    float* __restrict__ out,          // (n_mat, 64, 64)
    unsigned n_mat, unsigned per_cta)
{
    __shared__ alignas(128) float4 bufs[NBUF][1024];   // 2 x 16 KB

    unsigned tid = threadIdx.x;

    // One-time zero init of both buffers (pairs get overwritten each iter).
    #pragma unroll
    for (unsigned b = 0; b < NBUF; b++)
        #pragma unroll
        for (unsigned w = tid; w < 1024; w += THREADS)
            bufs[b][w] = make_float4(0.f, 0.f, 0.f, 0.f);

    // Per-thread constants: thread t owns output row t of each matrix.
    unsigned row  = tid;              // 0..63
    unsigned r0   = row & ~1u;        // even base row of the 2x2 block
    unsigned h    = row >> 1;         // 0..31
    bool     odd  = (row & 1u) != 0;
    bool     usey = (h & 16u) != 0;   // ch = h/16
    // inv_freq = 10000^(-(h%16)/16) = 2^(-(h%16) * log2(10000)/16)
    float invf = exp2f(-(float)(h & 15u) * (13.287712379549449f / 16.0f));

    unsigned base = blockIdx.x * per_cta;
    unsigned end  = base + per_cta; if (end > n_mat) end = n_mat;

    __syncthreads();

    unsigned it = 0;
    for (unsigned bs = base; bs < end; ++bs, ++it) {
        float* buf = (float*)bufs[it & (NBUF - 1)];

        // Make sure the bulk store issued NBUF iterations ago has finished
        // reading this buffer before we overwrite its pairs.
        if (it >= NBUF) {
            if (tid == 0)
                asm volatile("cp.async.bulk.wait_group %0;" :: "n"(NBUF - 1) : "memory");
            __syncthreads();
        }

        // Broadcast load of this matrix's (x, y).
        float2 xy = *reinterpret_cast<const float2*>(spa + (size_t)bs * 2u);
        float coord = usey ? xy.y : xy.x;
        float s, c;
        sincosf(coord * invf, &s, &c);
        float2 pr = odd ? make_float2(s, c) : make_float2(c, -s);
        *reinterpret_cast<float2*>(buf + (size_t)row * 64u + r0) = pr;

        // Order generic-proxy SMEM writes before the async-proxy bulk read.
        asm volatile("fence.proxy.async.shared::cta;" ::: "memory");
        __syncthreads();

        if (tid == 0) {
            uint32_t saddr;
            asm("{ .reg .u64 t; cvta.to.shared.u64 t, %1; cvt.u32.u64 %0, t; }"
                : "=r"(saddr) : "l"(buf));
            asm volatile(
                "cp.async.bulk.global.shared::cta.bulk_group [%0], [%1], %2;"
                :: "l"(out + (size_t)bs * 4096u), "r"(saddr), "n"(16384u)
                : "memory");
            asm volatile("cp.async.bulk.commit_group;" ::: "memory");
        }
    }

    // Drain all outstanding bulk stores before SMEM is deallocated.
    if (tid == 0)
        asm volatile("cp.async.bulk.wait_group 0;" ::: "memory");
}

extern "C" void kernel_launch(void* const* d_in, const int* in_sizes, int n_in,
                              void* d_out, int out_size)
{
    const float* spa = (const float*)d_in[0];
    float* out = (float*)d_out;

    unsigned n_mat = (unsigned)(out_size / 4096);   // 16384
    unsigned grid    = 1024;                        // single wave: <= 148 SMs * 7 CTAs
    unsigned per_cta = (n_mat + grid - 1) / grid;   // 16

    rope2d_persist_kernel<<<grid, THREADS>>>(spa, out, n_mat, per_cta);
}

// round 4
// speedup vs baseline: 1.1659x; 1.1659x over previous
#include <cuda_runtime.h>
#include <cstdint>

// Output: R[b, s, 64, 64] fp32, B*S = 16384 matrices of 16 KB each.
// Only 128 floats per matrix are nonzero (32 diagonal 2x2 blocks), and the
// nonzero LOCATIONS are identical for every matrix. Persistent CTAs zero
// NBUF SMEM buffers once, then per matrix overwrite only the 64 (sin,cos)
// pairs and stream the 16 KB buffer out with cp.async.bulk. NBUF=6 deep
// pipeline keeps ~6 bulk stores in flight per CTA so the TMA path never gaps.

static constexpr unsigned NBUF    = 6;      // 6 x 16 KB = 96 KB dynamic smem
static constexpr unsigned THREADS = 64;

__global__ void __launch_bounds__(THREADS) rope2d_deep_kernel(
    const float* __restrict__ spa,    // (n_mat, 2)
    float* __restrict__ out,          // (n_mat, 64, 64)
    unsigned n_mat, unsigned per_cta)
{
    extern __shared__ float4 bufs[];  // NBUF * 1024 float4

    unsigned tid = threadIdx.x;

    // One-time zero init of all buffers (pair slots get overwritten per iter).
    for (unsigned w = tid; w < NBUF * 1024u; w += THREADS)
        bufs[w] = make_float4(0.f, 0.f, 0.f, 0.f);

    // Thread t owns output row t of each matrix.
    unsigned row  = tid;              // 0..63
    unsigned r0   = row & ~1u;        // even base row of the 2x2 block
    unsigned h    = row >> 1;         // 0..31
    bool     odd  = (row & 1u) != 0;
    bool     usey = (h & 16u) != 0;   // channel = h/16
    // inv_freq = 10000^(-(h%16)/16) = 2^(-(h%16) * log2(10000)/16)
    float invf = exp2f(-(float)(h & 15u) * (13.287712379549449f / 16.0f));

    unsigned base = blockIdx.x * per_cta;
    unsigned end  = base + per_cta; if (end > n_mat) end = n_mat;

    __syncthreads();

    unsigned slot = 0, it = 0;
    for (unsigned bs = base; bs < end; ++bs, ++it) {
        float* buf = (float*)(bufs + (size_t)slot * 1024u);

        // Ensure the bulk store issued NBUF iterations ago has finished
        // READING this buffer (read-only wait) before overwriting its pairs.
        if (it >= NBUF) {
            if (tid == 0)
                asm volatile("cp.async.bulk.wait_group.read %0;"
                             :: "n"(NBUF - 1) : "memory");
            __syncthreads();
        }

        float2 xy = *reinterpret_cast<const float2*>(spa + (size_t)bs * 2u);
        float s, c;
        sincosf((usey ? xy.y : xy.x) * invf, &s, &c);
        float2 pr = odd ? make_float2(s, c) : make_float2(c, -s);
        *reinterpret_cast<float2*>(buf + (size_t)row * 64u + r0) = pr;

        // Order generic-proxy SMEM writes before the async-proxy bulk read.
        asm volatile("fence.proxy.async.shared::cta;" ::: "memory");
        __syncthreads();

        if (tid == 0) {
            uint32_t saddr;
            asm("{ .reg .u64 t; cvta.to.shared.u64 t, %1; cvt.u32.u64 %0, t; }"
                : "=r"(saddr) : "l"(buf));
            asm volatile(
                "cp.async.bulk.global.shared::cta.bulk_group [%0], [%1], %2;"
                :: "l"(out + (size_t)bs * 4096u), "r"(saddr), "n"(16384u)
                : "memory");
            asm volatile("cp.async.bulk.commit_group;" ::: "memory");
        }

        if (++slot == NBUF) slot = 0;
    }

    // Drain all outstanding bulk stores before SMEM is deallocated.
    if (tid == 0)
        asm volatile("cp.async.bulk.wait_group 0;" ::: "memory");
}

extern "C" void kernel_launch(void* const* d_in, const int* in_sizes, int n_in,
                              void* d_out, int out_size)
{
    const float* spa = (const float*)d_in[0];
    float* out = (float*)d_out;

    unsigned n_mat = (unsigned)(out_size / 4096);          // 16384
    unsigned grid  = 296;                                  // 2 CTAs/SM, one wave
    unsigned per_cta = (n_mat + grid - 1) / grid;          // 56

    size_t smem = (size_t)NBUF * 1024u * sizeof(float4);   // 96 KB
    cudaFuncSetAttribute(rope2d_deep_kernel,
                         cudaFuncAttributeMaxDynamicSharedMemorySize, (int)smem);
    rope2d_deep_kernel<<<grid, THREADS, smem>>>(spa, out, n_mat, per_cta);
}

// round 5
// speedup vs baseline: 1.1873x; 1.0184x over previous
#include <cuda_runtime.h>
#include <cstdint>

// Output: R[b, s, 64, 64] fp32, B*S = 16384 matrices of 16 KB each.
// Only 128 floats per matrix are nonzero (32 diagonal 2x2 blocks) and the
// nonzero LOCATIONS are identical for every matrix.
//
// Persistent CTAs: zero NBUF 16 KB SMEM buffers once, prefetch this CTA's
// spa slice into SMEM once, then per matrix overwrite only the 64 (sin,cos)
// pairs and stream the buffer out with cp.async.bulk (.read wait for reuse).
// 3 CTAs/SM x NBUF=4 keeps 12 bulk stores in flight per SM with three
// independent ~200-cycle issue chains, so the TMA/DRAM write stream never gaps.

static constexpr unsigned NBUF    = 4;      // 4 x 16 KB = 64 KB dynamic smem
static constexpr unsigned THREADS = 64;
static constexpr unsigned GRID    = 444;    // 148 SMs x 3 CTAs, single wave
static constexpr unsigned MAX_PER_CTA = 64; // per_cta = ceil(16384/444) = 37

__global__ void __launch_bounds__(THREADS, 3) rope2d_deep3_kernel(
    const float* __restrict__ spa,    // (n_mat, 2)
    float* __restrict__ out,          // (n_mat, 64, 64)
    unsigned n_mat, unsigned per_cta)
{
    extern __shared__ float4 bufs[];            // NBUF * 1024 float4
    __shared__ float2 spa_s[MAX_PER_CTA];       // this CTA's coord slice

    unsigned tid  = threadIdx.x;
    unsigned base = blockIdx.x * per_cta;
    unsigned cnt  = (base < n_mat) ? min(per_cta, n_mat - base) : 0u;

    // One-time zero init of all buffers (pair slots overwritten per iter).
    for (unsigned w = tid; w < NBUF * 1024u; w += THREADS)
        bufs[w] = make_float4(0.f, 0.f, 0.f, 0.f);

    // Prefetch this CTA's spa values (<= 296 B) into SMEM.
    for (unsigned i = tid; i < cnt; i += THREADS)
        spa_s[i] = reinterpret_cast<const float2*>(spa)[base + i];

    // Thread t owns output row t of each matrix.
    unsigned row  = tid;              // 0..63
    unsigned r0   = row & ~1u;        // even base row of the 2x2 block
    unsigned h    = row >> 1;         // 0..31
    bool     odd  = (row & 1u) != 0;
    bool     usey = (h & 16u) != 0;   // channel = h/16
    // inv_freq = 10000^(-(h%16)/16) = 2^(-(h%16) * log2(10000)/16)
    float invf = exp2f(-(float)(h & 15u) * (13.287712379549449f / 16.0f));

    __syncthreads();

    unsigned slot = 0;
    for (unsigned it = 0; it < cnt; ++it) {
        float* buf = (float*)(bufs + (size_t)slot * 1024u);

        // Ensure the store issued NBUF iterations ago finished READING
        // this buffer before we overwrite its pairs.
        if (it >= NBUF) {
            if (tid == 0)
                asm volatile("cp.async.bulk.wait_group.read %0;"
                             :: "n"(NBUF - 1) : "memory");
            __syncthreads();
        }

        float2 xy = spa_s[it];
        float s, c;
        sincosf((usey ? xy.y : xy.x) * invf, &s, &c);
        float2 pr = odd ? make_float2(s, c) : make_float2(c, -s);
        *reinterpret_cast<float2*>(buf + (size_t)row * 64u + r0) = pr;

        // Order generic-proxy SMEM writes before the async-proxy bulk read.
        asm volatile("fence.proxy.async.shared::cta;" ::: "memory");
        __syncthreads();

        if (tid == 0) {
            uint32_t saddr;
            asm("{ .reg .u64 t; cvta.to.shared.u64 t, %1; cvt.u32.u64 %0, t; }"
                : "=r"(saddr) : "l"(buf));
            asm volatile(
                "cp.async.bulk.global.shared::cta.bulk_group [%0], [%1], %2;"
                :: "l"(out + (size_t)(base + it) * 4096u), "r"(saddr), "n"(16384u)
                : "memory");
            asm volatile("cp.async.bulk.commit_group;" ::: "memory");
        }

        if (++slot == NBUF) slot = 0;
    }

    // Drain all outstanding bulk stores before SMEM is deallocated.
    if (tid == 0)
        asm volatile("cp.async.bulk.wait_group 0;" ::: "memory");
}

extern "C" void kernel_launch(void* const* d_in, const int* in_sizes, int n_in,
                              void* d_out, int out_size)
{
    const float* spa = (const float*)d_in[0];
    float* out = (float*)d_out;

    unsigned n_mat   = (unsigned)(out_size / 4096);        // 16384
    unsigned per_cta = (n_mat + GRID - 1) / GRID;          // 37

    size_t smem = (size_t)NBUF * 1024u * sizeof(float4);   // 64 KB
    cudaFuncSetAttribute(rope2d_deep3_kernel,
                         cudaFuncAttributeMaxDynamicSharedMemorySize, (int)smem);
    rope2d_deep3_kernel<<<GRID, THREADS, smem>>>(spa, out, n_mat, per_cta);
}

// round 6
// speedup vs baseline: 1.3596x; 1.1451x over previous
#include <cuda_runtime.h>
#include <cstdint>

// Output: R[b, s, 64, 64] fp32, 16384 matrices of 16 KB each.
// Per matrix: 32 diagonal 2x2 rotation blocks, zeros elsewhere.
//
// One CTA (128 threads) per matrix: build the 16 KB matrix in SMEM with a
// branch-light fill (8 unconditional zero STS.128 per thread + <=1 predicated
// pair overwrite), then stream it out with one cp.async.bulk. 14 CTAs/SM
// resident (224 KB smem) give 14 independent TMA commit chains per SM, and
// fresh CTAs keep the DRAM write stream dense.

static constexpr unsigned THREADS = 128;

__global__ void __launch_bounds__(THREADS) rope2d_lite_kernel(
    const float* __restrict__ spa,   // (n_mat, 2)
    float* __restrict__ out)         // (n_mat, 64, 64)
{
    __shared__ alignas(128) float4 tile[1024];   // 16 KB = one matrix

    unsigned tid = threadIdx.x;
    unsigned bs  = blockIdx.x;

    // ---- per-thread match decode (slots tid + 128k, k=0..7) --------------
    // slot w: row = w>>4, f4col = w&15. Pair lives in f4col == row>>2.
    // With 128-thread stride: row_k = 8k + (tid>>4); f4 = tid&15.
    // Match iff 2k + (tid>>6) == f4  ->  at most one k per thread.
    unsigned f4   = tid & 15u;
    int      diff = (int)f4 - (int)(tid >> 6);
    bool   match  = (diff >= 0) && ((diff & 1) == 0);
    unsigned kم   = (unsigned)diff >> 1;            // matching k if match
    unsigned row  = 8u * kم + (tid >> 4);           // matched output row

    // ---- pair value (only meaningful when match) --------------------------
    float4 pv = make_float4(0.f, 0.f, 0.f, 0.f);
    if (match) {
        float2 xy = *reinterpret_cast<const float2*>(spa + (size_t)bs * 2u);
        unsigned h = row >> 1;                      // 0..31
        float coord = (h & 16u) ? xy.y : xy.x;
        // inv_freq = 10000^(-(h%16)/16) = 2^(-(h%16)*log2(10000)/16)
        float invf = exp2f(-(float)(h & 15u) * (13.287712379549449f / 16.0f));
        float s, c;
        __sincosf(coord * invf, &s, &c);
        float a, b;
        if (row & 1u) { a = s; b = c;  }            // odd row:  (sin, cos)
        else          { a = c; b = -s; }            // even row: (cos, -sin)
        unsigned r0 = row & ~1u;
        if (r0 & 2u) { pv.z = a; pv.w = b; }        // pair at lanes 2,3
        else         { pv.x = a; pv.y = b; }        // pair at lanes 0,1
    }

    // ---- fill: 8 unconditional zero stores, then one predicated overwrite -
    const float4 z = make_float4(0.f, 0.f, 0.f, 0.f);
    #pragma unroll
    for (unsigned k = 0; k < 8; k++)
        tile[tid + 128u * k] = z;
    if (match)
        tile[tid + 128u * kم] = pv;

    // ---- bulk store SMEM -> GMEM ------------------------------------------
    asm volatile("fence.proxy.async.shared::cta;" ::: "memory");
    __syncthreads();

    if (tid == 0) {
        uint32_t saddr;
        asm("{ .reg .u64 t; cvta.to.shared.u64 t, %1; cvt.u32.u64 %0, t; }"
            : "=r"(saddr) : "l"(tile));
        asm volatile(
            "cp.async.bulk.global.shared::cta.bulk_group [%0], [%1], %2;"
            :: "l"(out + (size_t)bs * 4096u), "r"(saddr), "n"(16384u)
            : "memory");
        asm volatile("cp.async.bulk.commit_group;" ::: "memory");
        // SMEM is freed on CTA exit; wait until TMA has read it out.
        asm volatile("cp.async.bulk.wait_group.read 0;" ::: "memory");
    }
}

extern "C" void kernel_launch(void* const* d_in, const int* in_sizes, int n_in,
                              void* d_out, int out_size)
{
    const float* spa = (const float*)d_in[0];
    float* out = (float*)d_out;

    unsigned n_mat = (unsigned)(out_size / 4096);   // 16384
    rope2d_lite_kernel<<<n_mat, THREADS>>>(spa, out);
}